// round 1
// baseline (speedup 1.0000x reference)
#include <cuda_runtime.h>
#include <math.h>

#define NMAX 16384
#define GMAX 1024
#define PI_F 3.14159265358979323846f

// ---------------- device scratch (no allocation allowed) ----------------
__device__ float g_node_f[NMAX * 2];   // per-node features after node MLP (+updates in multi-hop path)
__device__ float g_eAB[NMAX * 2];      // edge_f[ge[:,0]] (masked)
__device__ float g_upd[NMAX * 2];      // per-row upd (multi-hop path only)
__device__ float g_seg[GMAX * 2];      // per-graph sums
__device__ float g_cnt[GMAX];          // per-graph node counts

__device__ __forceinline__ float leaky(float x) { return x > 0.f ? x : 0.2f * x; }

// ---------------- 5-qubit gate helpers (state fully in registers) -------
// local bit map: q0->bit0(1), q3->bit1(2), q4->bit2(4), q7->bit3(8), q8->bit4(16)

template<int BIT>
__device__ __forceinline__ void ry_gate(float* re, float* im, float c, float s) {
#pragma unroll
    for (int m = 0; m < 32; m++) if (!(m & BIT)) {
        int m1 = m | BIT;
        float r0 = re[m], i0 = im[m], r1 = re[m1], i1 = im[m1];
        re[m]  = c * r0 - s * r1;  im[m]  = c * i0 - s * i1;
        re[m1] = s * r0 + c * r1;  im[m1] = s * i0 + c * i1;
    }
}

template<int BIT>
__device__ __forceinline__ void rx_gate(float* re, float* im, float c, float s) {
    // [[c, -i s], [-i s, c]]
#pragma unroll
    for (int m = 0; m < 32; m++) if (!(m & BIT)) {
        int m1 = m | BIT;
        float r0 = re[m], i0 = im[m], r1 = re[m1], i1 = im[m1];
        re[m]  = c * r0 + s * i1;  im[m]  = c * i0 - s * r1;
        re[m1] = c * r1 + s * i0;  im[m1] = c * i1 - s * r0;
    }
}

template<int BIT>
__device__ __forceinline__ void rz_gate(float* re, float* im, float c, float s) {
    // diag(e^{-i t/2}, e^{+i t/2})
#pragma unroll
    for (int m = 0; m < 32; m++) {
        float r = re[m], ii = im[m];
        if (m & BIT) { re[m] = c * r - s * ii; im[m] = c * ii + s * r; }
        else         { re[m] = c * r + s * ii; im[m] = c * ii - s * r; }
    }
}

template<int CBIT, int TBIT>
__device__ __forceinline__ void cry_gate(float* re, float* im, float c, float s) {
#pragma unroll
    for (int m = 0; m < 32; m++) if ((m & CBIT) && !(m & TBIT)) {
        int m1 = m | TBIT;
        float r0 = re[m], i0 = im[m], r1 = re[m1], i1 = im[m1];
        re[m]  = c * r0 - s * r1;  im[m]  = c * i0 - s * i1;
        re[m1] = s * r0 + c * r1;  im[m1] = s * i0 + c * i1;
    }
}

template<int CBIT, int TBIT>
__device__ __forceinline__ void crx_gate(float* re, float* im, float c, float s) {
#pragma unroll
    for (int m = 0; m < 32; m++) if ((m & CBIT) && !(m & TBIT)) {
        int m1 = m | TBIT;
        float r0 = re[m], i0 = im[m], r1 = re[m1], i1 = im[m1];
        re[m]  = c * r0 + s * i1;  im[m]  = c * i0 - s * r1;
        re[m1] = c * r1 + s * i0;  im[m1] = c * i1 - s * r0;
    }
}

template<int CBIT, int TBIT>
__device__ __forceinline__ void crz_gate(float* re, float* im, float c, float s) {
#pragma unroll
    for (int m = 0; m < 32; m++) if (m & CBIT) {
        float r = re[m], ii = im[m];
        if (m & TBIT) { re[m] = c * r - s * ii; im[m] = c * ii + s * r; }
        else          { re[m] = c * r + s * ii; im[m] = c * ii - s * r; }
    }
}

template<int B1, int B2>
__device__ __forceinline__ void cz_gate(float* re, float* im) {
#pragma unroll
    for (int m = 0; m < 32; m++) if ((m & B1) && (m & B2)) { re[m] = -re[m]; im[m] = -im[m]; }
}

// ---------------- K1: node MLP (all nodes) + edge MLP (used edges) + zero accumulators
__global__ void k1_feat(const float* __restrict__ node_feat, int N,
                        const float* __restrict__ edge_attr,
                        const float* __restrict__ nW1, const float* __restrict__ nb1,
                        const float* __restrict__ nW2, const float* __restrict__ nb2,
                        const float* __restrict__ eW1, const float* __restrict__ eb1,
                        const float* __restrict__ eW2, const float* __restrict__ eb2,
                        const int* __restrict__ ge)
{
    __shared__ float sW1[16 * 128], sb1[128], sW2[256], sb2[2];
    __shared__ float tW1[8 * 128], tb1[128], tW2[256], tb2[2];
    int tid = threadIdx.x;
    for (int j = tid; j < 16 * 128; j += blockDim.x) sW1[j] = nW1[j];
    for (int j = tid; j < 8 * 128;  j += blockDim.x) tW1[j] = eW1[j];
    for (int j = tid; j < 128; j += blockDim.x) { sb1[j] = nb1[j]; tb1[j] = eb1[j]; }
    for (int j = tid; j < 256; j += blockDim.x) { sW2[j] = nW2[j]; tW2[j] = eW2[j]; }
    if (tid < 2) { sb2[tid] = nb2[tid]; tb2[tid] = eb2[tid]; }
    __syncthreads();

    int i = blockIdx.x * blockDim.x + tid;
    // zero per-graph accumulators (grid-stride; K1 always runs before atomics)
    for (int j = i; j < GMAX * 3; j += gridDim.x * blockDim.x) {
        if (j < GMAX * 2) g_seg[j] = 0.f; else g_cnt[j - GMAX * 2] = 0.f;
    }
    if (i >= N) return;

    // node MLP: 16 -> 128 (leaky 0.2) -> 2, tanh * pi
    float x[16];
#pragma unroll
    for (int k = 0; k < 16; k++) x[k] = node_feat[i * 16 + k];
    float o0 = sb2[0], o1 = sb2[1];
    for (int j = 0; j < 128; j++) {
        float h = sb1[j];
#pragma unroll
        for (int k = 0; k < 16; k++) h = fmaf(x[k], sW1[k * 128 + j], h);
        h = leaky(h);
        o0 = fmaf(h, sW2[j * 2 + 0], o0);
        o1 = fmaf(h, sW2[j * 2 + 1], o1);
    }
    g_node_f[i * 2 + 0] = tanhf(o0) * PI_F;
    g_node_f[i * 2 + 1] = tanhf(o1) * PI_F;

    // edge MLP only for the one used edge per row: ge[i,0]
    int eidx = ge[i * 3];
    float eA = 0.f, eB = 0.f;
    if (eidx >= 0) {
        float y[8];
#pragma unroll
        for (int k = 0; k < 8; k++) y[k] = edge_attr[eidx * 8 + k];
        float p0 = tb2[0], p1 = tb2[1];
        for (int j = 0; j < 128; j++) {
            float h = tb1[j];
#pragma unroll
            for (int k = 0; k < 8; k++) h = fmaf(y[k], tW1[k * 128 + j], h);
            h = leaky(h);
            p0 = fmaf(h, tW2[j * 2 + 0], p0);
            p1 = fmaf(h, tW2[j * 2 + 1], p1);
        }
        eA = tanhf(p0) * PI_F;
        eB = tanhf(p1) * PI_F;
    }
    g_eAB[i * 2 + 0] = eA;
    g_eAB[i * 2 + 1] = eB;
}

// ---------------- shared PQC core ----------------
__device__ __forceinline__ float pqc_exp(float eA, float eB, float nA0, float nA1,
                                         float nB0, float nB1,
                                         const float* tc, const float* ts)
{
    float cA, sA, cB, sB, c3a, s3a, c3b, s3b, c4a, s4a, c4b, s4b;
    sincosf(0.5f * eA,  &sA,  &cA);
    sincosf(0.5f * eB,  &sB,  &cB);
    sincosf(0.5f * nA0, &s3a, &c3a);
    sincosf(0.5f * nA1, &s3b, &c3b);
    sincosf(0.5f * nB0, &s4a, &c4a);
    sincosf(0.5f * nB1, &s4b, &c4b);

    float re[32], im[32];
#pragma unroll
    for (int m = 0; m < 32; m++) { re[m] = 0.f; im[m] = 0.f; }

    // product state on bits 0..2 (RZ·RY|0>); q7,q8 (bits 3,4) start at |0>
    float p0r[2], p0i[2], p1r[2], p1i[2], p2r[2], p2i[2];
    p0r[0] = cA * cB;   p0i[0] = -cA * sB;   p0r[1] = sA * cB;   p0i[1] = sA * sB;
    p1r[0] = c3a * c3b; p1i[0] = -c3a * s3b; p1r[1] = s3a * c3b; p1i[1] = s3a * s3b;
    p2r[0] = c4a * c4b; p2i[0] = -c4a * s4b; p2r[1] = s4a * c4b; p2i[1] = s4a * s4b;
#pragma unroll
    for (int m = 0; m < 8; m++) {
        int b0 = m & 1, b1 = (m >> 1) & 1, b2 = (m >> 2) & 1;
        float ar = p0r[b0] * p1r[b1] - p0i[b0] * p1i[b1];
        float ai = p0r[b0] * p1i[b1] + p0i[b0] * p1r[b1];
        re[m] = ar * p2r[b2] - ai * p2i[b2];
        im[m] = ar * p2i[b2] + ai * p2r[b2];
    }

    // controlled entanglers: CRX(nB0) 4->7, CRY(eA) 0->7, CRZ(nB1) 4->8, CRY(eB) 0->8
    crx_gate<4, 8>(re, im, c4a, s4a);
    cry_gate<1, 8>(re, im, cA, sA);
    crz_gate<4, 16>(re, im, c4b, s4b);
    cry_gate<1, 16>(re, im, cB, sB);

    // block 0: qubits (0,4,7) = bits (1,4,8), theta 0..8
    rx_gate<1>(re, im, tc[0], ts[0]);  ry_gate<1>(re, im, tc[1], ts[1]);  rz_gate<1>(re, im, tc[2], ts[2]);
    rx_gate<4>(re, im, tc[3], ts[3]);  ry_gate<4>(re, im, tc[4], ts[4]);  rz_gate<4>(re, im, tc[5], ts[5]);
    rx_gate<8>(re, im, tc[6], ts[6]);  ry_gate<8>(re, im, tc[7], ts[7]);  rz_gate<8>(re, im, tc[8], ts[8]);
    cz_gate<1, 4>(re, im); cz_gate<4, 8>(re, im); cz_gate<8, 1>(re, im);

    // block 1: qubits (7,4,8) = bits (8,4,16), theta 9..17
    rx_gate<8>(re, im, tc[9],  ts[9]);  ry_gate<8>(re, im, tc[10], ts[10]);  rz_gate<8>(re, im, tc[11], ts[11]);
    rx_gate<4>(re, im, tc[12], ts[12]); ry_gate<4>(re, im, tc[13], ts[13]);  rz_gate<4>(re, im, tc[14], ts[14]);
    rx_gate<16>(re, im, tc[15], ts[15]); ry_gate<16>(re, im, tc[16], ts[16]); rz_gate<16>(re, im, tc[17], ts[17]);
    cz_gate<8, 4>(re, im); cz_gate<4, 16>(re, im); cz_gate<16, 8>(re, im);

    // block 2: qubits (3,7,8) = bits (2,8,16), theta 18..26
    rx_gate<2>(re, im, tc[18], ts[18]); ry_gate<2>(re, im, tc[19], ts[19]); rz_gate<2>(re, im, tc[20], ts[20]);
    rx_gate<8>(re, im, tc[21], ts[21]); ry_gate<8>(re, im, tc[22], ts[22]); rz_gate<8>(re, im, tc[23], ts[23]);
    rx_gate<16>(re, im, tc[24], ts[24]); ry_gate<16>(re, im, tc[25], ts[25]); rz_gate<16>(re, im, tc[26], ts[26]);
    cz_gate<2, 8>(re, im); cz_gate<8, 16>(re, im); cz_gate<16, 2>(re, im);

    // <psi| X_(q3) |psi> : flip local bit 1 (value 2)
    float ex = 0.f;
#pragma unroll
    for (int m = 0; m < 32; m++) ex += re[m] * re[m ^ 2] + im[m] * im[m ^ 2];
    return ex;
}

// ---------------- K2: PQC + upd MLP; fused mode adds straight into graph accumulators
// mode==1 (single hop): atomicAdd node_f[i] + upd into seg/cnt (telescoped scatter+segment-sum)
// mode==0 (multi-hop step): write upd to g_upd
__global__ void k2_pqc(int N, int mode,
                       const float* __restrict__ theta,
                       const float* __restrict__ uW1, const float* __restrict__ ub1,
                       const float* __restrict__ uW2, const float* __restrict__ ub2,
                       const int* __restrict__ gn, const int* __restrict__ batch)
{
    __shared__ float tc[27], ts[27];
    __shared__ float sW1[3 * 128], sb1[128], sW2[256], sb2[2];
    int tid = threadIdx.x;
    if (tid < 27) { float s, c; sincosf(0.5f * theta[tid], &s, &c); tc[tid] = c; ts[tid] = s; }
    for (int j = tid; j < 3 * 128; j += blockDim.x) sW1[j] = uW1[j];
    for (int j = tid; j < 128; j += blockDim.x) sb1[j] = ub1[j];
    for (int j = tid; j < 256; j += blockDim.x) sW2[j] = uW2[j];
    if (tid < 2) sb2[tid] = ub2[tid];
    __syncthreads();

    int i = blockIdx.x * blockDim.x + tid;
    if (i >= N) return;

    int i0 = gn[i * 4 + 0], i1 = gn[i * 4 + 1];
    int i0c = max(i0, 0), i1c = max(i1, 0);
    float nf0u = g_node_f[i0c * 2 + 0];         // unmasked (upd MLP input uses clipped gather)
    float nf1u = g_node_f[i0c * 2 + 1];
    float nA0 = (i0 >= 0) ? nf0u : 0.f;
    float nA1 = (i0 >= 0) ? nf1u : 0.f;
    float nB0 = (i1 >= 0) ? g_node_f[i1c * 2 + 0] : 0.f;
    float nB1 = (i1 >= 0) ? g_node_f[i1c * 2 + 1] : 0.f;
    float eA = g_eAB[i * 2 + 0], eB = g_eAB[i * 2 + 1];

    float ex = pqc_exp(eA, eB, nA0, nA1, nB0, nB1, tc, ts);

    // upd MLP: (nf0u, nf1u, ex) -> 128 (leaky) -> 2
    float u0 = sb2[0], u1 = sb2[1];
    for (int j = 0; j < 128; j++) {
        float h = sb1[j];
        h = fmaf(nf0u, sW1[j], h);
        h = fmaf(nf1u, sW1[128 + j], h);
        h = fmaf(ex,   sW1[256 + j], h);
        h = leaky(h);
        u0 = fmaf(h, sW2[j * 2 + 0], u0);
        u1 = fmaf(h, sW2[j * 2 + 1], u1);
    }

    if (mode == 1) {
        int gi = batch[i];
        atomicAdd(&g_seg[gi * 2 + 0], g_node_f[i * 2 + 0]);
        atomicAdd(&g_seg[gi * 2 + 1], g_node_f[i * 2 + 1]);
        atomicAdd(&g_cnt[gi], 1.f);
        int gt = batch[i0c];
        atomicAdd(&g_seg[gt * 2 + 0], u0);
        atomicAdd(&g_seg[gt * 2 + 1], u1);
    } else {
        g_upd[i * 2 + 0] = u0;
        g_upd[i * 2 + 1] = u1;
    }
}

// multi-hop scatter: node_f[gn[i,0]] += upd[i]
__global__ void k2_scatter(int N, const int* __restrict__ gn)
{
    int i = blockIdx.x * blockDim.x + threadIdx.x;
    if (i >= N) return;
    int t = max(gn[i * 4], 0);
    atomicAdd(&g_node_f[t * 2 + 0], g_upd[i * 2 + 0]);
    atomicAdd(&g_node_f[t * 2 + 1], g_upd[i * 2 + 1]);
}

// multi-hop final segment sums
__global__ void k_seg(int N, const int* __restrict__ batch)
{
    int i = blockIdx.x * blockDim.x + threadIdx.x;
    if (i >= N) return;
    int g = batch[i];
    atomicAdd(&g_seg[g * 2 + 0], g_node_f[i * 2 + 0]);
    atomicAdd(&g_seg[g * 2 + 1], g_node_f[i * 2 + 1]);
    atomicAdd(&g_cnt[g], 1.f);
}

// ---------------- K3: per-graph mean + head MLP (2->2 leaky ->2)
__global__ void k3_head(int G,
                        const float* __restrict__ hW1, const float* __restrict__ hb1,
                        const float* __restrict__ hW2, const float* __restrict__ hb2,
                        float* __restrict__ out)
{
    int g = blockIdx.x * blockDim.x + threadIdx.x;
    if (g >= G) return;
    float c = g_cnt[g];
    float inv = (c > 0.f) ? (1.f / c) : 0.f;
    float e0 = g_seg[g * 2 + 0] * inv;
    float e1 = g_seg[g * 2 + 1] * inv;
    float h0 = leaky(e0 * hW1[0] + e1 * hW1[2] + hb1[0]);
    float h1 = leaky(e0 * hW1[1] + e1 * hW1[3] + hb1[1]);
    out[g * 2 + 0] = h0 * hW2[0] + h1 * hW2[2] + hb2[0];
    out[g * 2 + 1] = h0 * hW2[1] + h1 * hW2[3] + hb2[1];
}

extern "C" void kernel_launch(void* const* d_in, const int* in_sizes, int n_in,
                              void* d_out, int out_size)
{
    const float* node_feat = (const float*)d_in[0];
    const float* edge_attr = (const float*)d_in[1];
    const float* nW1 = (const float*)d_in[2];
    const float* nb1 = (const float*)d_in[3];
    const float* nW2 = (const float*)d_in[4];
    const float* nb2 = (const float*)d_in[5];
    const float* eW1 = (const float*)d_in[6];
    const float* eb1 = (const float*)d_in[7];
    const float* eW2 = (const float*)d_in[8];
    const float* eb2 = (const float*)d_in[9];
    const float* theta = (const float*)d_in[10];
    const float* uW1 = (const float*)d_in[11];
    const float* ub1 = (const float*)d_in[12];
    const float* uW2 = (const float*)d_in[13];
    const float* ub2 = (const float*)d_in[14];
    const float* hW1 = (const float*)d_in[15];
    const float* hb1 = (const float*)d_in[16];
    const float* hW2 = (const float*)d_in[17];
    const float* hb2 = (const float*)d_in[18];
    const int* gn = (const int*)d_in[19];
    const int* ge = (const int*)d_in[20];
    const int* batch = (const int*)d_in[21];

    int N = in_sizes[0] / 16;
    int H = in_sizes[10] / 27;      // hops (1 for this dataset)
    int G = out_size / 2;           // num_graphs from output shape

    const int T = 128;
    int nb = (N + T - 1) / T;

    k1_feat<<<nb, T>>>(node_feat, N, edge_attr, nW1, nb1, nW2, nb2,
                       eW1, eb1, eW2, eb2, ge);

    if (H == 1) {
        // fused: pqc + upd + telescoped scatter/segment-sum in one kernel
        k2_pqc<<<nb, T>>>(N, 1, theta, uW1, ub1, uW2, ub2, gn, batch);
    } else {
        for (int h = 0; h < H; h++) {
            k2_pqc<<<nb, T>>>(N, 0, theta + 27 * h,
                              uW1 + 384 * h, ub1 + 128 * h,
                              uW2 + 256 * h, ub2 + 2 * h, gn, batch);
            k2_scatter<<<nb, T>>>(N, gn);
        }
        k_seg<<<nb, T>>>(N, batch);
    }

    k3_head<<<(G + 127) / 128, 128>>>(G, hW1, hb1, hW2, hb2, (float*)d_out);
}

// round 2
// speedup vs baseline: 1.1998x; 1.1998x over previous
#include <cuda_runtime.h>
#include <math.h>

#define NMAX 16384
#define GMAX 1024
#define PI_F 3.14159265358979323846f

__device__ float g_node_f[NMAX * 2];
__device__ float g_eAB[NMAX * 2];
__device__ float g_upd[NMAX * 2];
__device__ float g_seg[GMAX * 2];
__device__ float g_cnt[GMAX];

__device__ __forceinline__ float leaky(float x) { return x > 0.f ? x : 0.2f * x; }

// ---------------- K1: warp-per-row node MLP + edge MLP -------------------
// block = 128 (4 warps) -> 4 rows per block. Lane l computes hidden units
// j = l + 32u (u=0..3); outputs reduced by warp shuffle.
__global__ void k1_feat(const float* __restrict__ node_feat, int N,
                        const float* __restrict__ edge_attr,
                        const float* __restrict__ nW1, const float* __restrict__ nb1,
                        const float* __restrict__ nW2, const float* __restrict__ nb2,
                        const float* __restrict__ eW1, const float* __restrict__ eb1,
                        const float* __restrict__ eW2, const float* __restrict__ eb2,
                        const int* __restrict__ ge)
{
    int tid = threadIdx.x;
    int lane = tid & 31;
    int wrp = tid >> 5;
    int gtid = blockIdx.x * blockDim.x + tid;

    // zero per-graph accumulators
    if (gtid < GMAX * 2) g_seg[gtid] = 0.f;
    else if (gtid < GMAX * 3) g_cnt[gtid - GMAX * 2] = 0.f;

    int i = blockIdx.x * 4 + wrp;
    int ic = min(i, N - 1);
    bool valid = i < N;

    // ---- node MLP: 16 -> 128 (leaky) -> 2
    float x[16];
#pragma unroll
    for (int k = 0; k < 16; k++) x[k] = __ldg(node_feat + ic * 16 + k);

    float o0 = 0.f, o1 = 0.f;
#pragma unroll
    for (int u = 0; u < 4; u++) {
        int j = lane + 32 * u;
        float h = __ldg(nb1 + j);
#pragma unroll
        for (int k = 0; k < 16; k++) h = fmaf(x[k], __ldg(nW1 + k * 128 + j), h);
        h = leaky(h);
        o0 = fmaf(h, __ldg(nW2 + 2 * j + 0), o0);
        o1 = fmaf(h, __ldg(nW2 + 2 * j + 1), o1);
    }
#pragma unroll
    for (int off = 16; off >= 1; off >>= 1) {
        o0 += __shfl_xor_sync(0xffffffffu, o0, off);
        o1 += __shfl_xor_sync(0xffffffffu, o1, off);
    }

    // ---- edge MLP for ge[i,0]: 8 -> 128 (leaky) -> 2
    int eidx = __ldg(ge + ic * 3);
    int ec = max(eidx, 0);
    float y[8];
#pragma unroll
    for (int k = 0; k < 8; k++) y[k] = __ldg(edge_attr + ec * 8 + k);

    float p0 = 0.f, p1 = 0.f;
#pragma unroll
    for (int u = 0; u < 4; u++) {
        int j = lane + 32 * u;
        float h = __ldg(eb1 + j);
#pragma unroll
        for (int k = 0; k < 8; k++) h = fmaf(y[k], __ldg(eW1 + k * 128 + j), h);
        h = leaky(h);
        p0 = fmaf(h, __ldg(eW2 + 2 * j + 0), p0);
        p1 = fmaf(h, __ldg(eW2 + 2 * j + 1), p1);
    }
#pragma unroll
    for (int off = 16; off >= 1; off >>= 1) {
        p0 += __shfl_xor_sync(0xffffffffu, p0, off);
        p1 += __shfl_xor_sync(0xffffffffu, p1, off);
    }

    if (lane == 0 && valid) {
        g_node_f[i * 2 + 0] = tanhf(o0 + __ldg(nb2 + 0)) * PI_F;
        g_node_f[i * 2 + 1] = tanhf(o1 + __ldg(nb2 + 1)) * PI_F;
        g_eAB[i * 2 + 0] = (eidx >= 0) ? tanhf(p0 + __ldg(eb2 + 0)) * PI_F : 0.f;
        g_eAB[i * 2 + 1] = (eidx >= 0) ? tanhf(p1 + __ldg(eb2 + 1)) * PI_F : 0.f;
    }
}

// ---------------- split-state gate helpers ------------------------------
// 5-qubit state, 4 threads/row. Local bits: q0->1, q3->2, q4->4.
// Thread-lane bits: q7 -> lane xor 1, q8 -> lane xor 2.
// U layout: [00r,00i,01r,01i,10r,10i,11r,11i]

template<int B>
__device__ __forceinline__ void local_u(float* vr, float* vi, const float* U) {
#pragma unroll
    for (int m = 0; m < 8; m++) if (!(m & B)) {
        int m1 = m | B;
        float r0 = vr[m], i0 = vi[m], r1 = vr[m1], i1 = vi[m1];
        vr[m]  = U[0]*r0 - U[1]*i0 + U[2]*r1 - U[3]*i1;
        vi[m]  = U[0]*i0 + U[1]*r0 + U[2]*i1 + U[3]*r1;
        vr[m1] = U[4]*r0 - U[5]*i0 + U[6]*r1 - U[7]*i1;
        vi[m1] = U[4]*i0 + U[5]*r0 + U[6]*i1 + U[7]*r1;
    }
}

template<int TB>
__device__ __forceinline__ void cross_u(float* vr, float* vi, int t, const float* U) {
    float Cmr = t ? U[6] : U[0], Cmi = t ? U[7] : U[1];
    float Cpr = t ? U[4] : U[2], Cpi = t ? U[5] : U[3];
#pragma unroll
    for (int m = 0; m < 8; m++) {
        float pr = __shfl_xor_sync(0xffffffffu, vr[m], TB);
        float pi = __shfl_xor_sync(0xffffffffu, vi[m], TB);
        float nr = Cmr*vr[m] - Cmi*vi[m] + Cpr*pr - Cpi*pi;
        float ni = Cmr*vi[m] + Cmi*vr[m] + Cpr*pi + Cpi*pr;
        vr[m] = nr; vi[m] = ni;
    }
}

// ---------------- K2: split-state PQC + upd MLP -------------------------
// block = 64 threads = 16 rows * 4 threads.
__global__ void k2_pqc(int N, int mode,
                       const float* __restrict__ theta,
                       const float* __restrict__ uW1, const float* __restrict__ ub1,
                       const float* __restrict__ uW2, const float* __restrict__ ub2,
                       const int* __restrict__ gn, const int* __restrict__ batch)
{
    __shared__ float sU[9][8];
    __shared__ float sW1[384], sb1[128], sW2[256], sb2v[2];
    int tid = threadIdx.x;

    // combined U = Rz * Ry * Rx per gate triple (theta only)
    if (tid < 9) {
        int g = tid;
        float sx, cx, sy, cy, sz, cz;
        sincosf(0.5f * theta[3 * g + 0], &sx, &cx);
        sincosf(0.5f * theta[3 * g + 1], &sy, &cy);
        sincosf(0.5f * theta[3 * g + 2], &sz, &cz);
        float M00r =  cy*cx, M00i =  sy*sx;
        float M01r = -sy*cx, M01i = -cy*sx;
        float M10r =  sy*cx, M10i = -cy*sx;
        float M11r =  cy*cx, M11i = -sy*sx;
        sU[g][0] = cz*M00r + sz*M00i;  sU[g][1] = cz*M00i - sz*M00r;
        sU[g][2] = cz*M01r + sz*M01i;  sU[g][3] = cz*M01i - sz*M01r;
        sU[g][4] = cz*M10r - sz*M10i;  sU[g][5] = cz*M10i + sz*M10r;
        sU[g][6] = cz*M11r - sz*M11i;  sU[g][7] = cz*M11i + sz*M11r;
    }
    for (int j = tid; j < 384; j += blockDim.x) sW1[j] = uW1[j];
    for (int j = tid; j < 128; j += blockDim.x) sb1[j] = ub1[j];
    for (int j = tid; j < 256; j += blockDim.x) sW2[j] = uW2[j];
    if (tid < 2) sb2v[tid] = ub2[tid];
    __syncthreads();

    int row = blockIdx.x * (blockDim.x >> 2) + (tid >> 2);
    int sub = tid & 3;
    int i = min(row, N - 1);
    bool valid = row < N;

    int i0 = __ldg(gn + i * 4 + 0), i1 = __ldg(gn + i * 4 + 1);
    int i0c = max(i0, 0), i1c = max(i1, 0);
    float nf0u = g_node_f[i0c * 2 + 0];
    float nf1u = g_node_f[i0c * 2 + 1];
    float nA0 = (i0 >= 0) ? nf0u : 0.f;
    float nA1 = (i0 >= 0) ? nf1u : 0.f;
    float nB0 = (i1 >= 0) ? g_node_f[i1c * 2 + 0] : 0.f;
    float nB1 = (i1 >= 0) ? g_node_f[i1c * 2 + 1] : 0.f;
    float eA = g_eAB[i * 2 + 0], eB = g_eAB[i * 2 + 1];

    float cA, sA, cB, sB, c3a, s3a, c3b, s3b, c4a, s4a, c4b, s4b;
    sincosf(0.5f * eA,  &sA,  &cA);
    sincosf(0.5f * eB,  &sB,  &cB);
    sincosf(0.5f * nA0, &s3a, &c3a);
    sincosf(0.5f * nA1, &s3b, &c3b);
    sincosf(0.5f * nB0, &s4a, &c4a);
    sincosf(0.5f * nB1, &s4b, &c4b);

    // product state on local bits (q0,q3,q4); q7=q8=|0> => only sub==0 nonzero
    float p0r[2], p0i[2], p1r[2], p1i[2], p2r[2], p2i[2];
    p0r[0] = cA*cB;    p0i[0] = -cA*sB;   p0r[1] = sA*cB;    p0i[1] = sA*sB;
    p1r[0] = c3a*c3b;  p1i[0] = -c3a*s3b; p1r[1] = s3a*c3b;  p1i[1] = s3a*s3b;
    p2r[0] = c4a*c4b;  p2i[0] = -c4a*s4b; p2r[1] = s4a*c4b;  p2i[1] = s4a*s4b;

    float msk = (sub == 0) ? 1.f : 0.f;
    float vr[8], vi[8];
#pragma unroll
    for (int m = 0; m < 8; m++) {
        int b0 = m & 1, b1 = (m >> 1) & 1, b2 = (m >> 2) & 1;
        float ar = p0r[b0]*p1r[b1] - p0i[b0]*p1i[b1];
        float ai = p0r[b0]*p1i[b1] + p0i[b0]*p1r[b1];
        vr[m] = msk * (ar*p2r[b2] - ai*p2i[b2]);
        vi[m] = msk * (ar*p2i[b2] + ai*p2r[b2]);
    }

    int t7 = sub & 1, t8 = (sub >> 1) & 1;

    // CRX(nB0): control q4 (m&4), target q7 (lane xor 1). Symmetric coeffs.
#pragma unroll
    for (int m = 0; m < 8; m++) if (m & 4) {
        float pr = __shfl_xor_sync(0xffffffffu, vr[m], 1);
        float pi = __shfl_xor_sync(0xffffffffu, vi[m], 1);
        float nr = c4a*vr[m] + s4a*pi;
        float ni = c4a*vi[m] - s4a*pr;
        vr[m] = nr; vi[m] = ni;
    }
    // CRY(eA): control q0 (m&1), target q7
    {
        float ss = t7 ? sA : -sA;
#pragma unroll
        for (int m = 0; m < 8; m++) if (m & 1) {
            float pr = __shfl_xor_sync(0xffffffffu, vr[m], 1);
            float pi = __shfl_xor_sync(0xffffffffu, vi[m], 1);
            vr[m] = cA*vr[m] + ss*pr;
            vi[m] = cA*vi[m] + ss*pi;
        }
    }
    // CRZ(nB1): control q4 (m&4), target q8 (diagonal -> local phase)
    {
        float zs = t8 ? s4b : -s4b;
#pragma unroll
        for (int m = 0; m < 8; m++) if (m & 4) {
            float r = vr[m], ii = vi[m];
            vr[m] = c4b*r - zs*ii;
            vi[m] = c4b*ii + zs*r;
        }
    }
    // CRY(eB): control q0 (m&1), target q8 (lane xor 2)
    {
        float ss = t8 ? sB : -sB;
#pragma unroll
        for (int m = 0; m < 8; m++) if (m & 1) {
            float pr = __shfl_xor_sync(0xffffffffu, vr[m], 2);
            float pi = __shfl_xor_sync(0xffffffffu, vi[m], 2);
            vr[m] = cB*vr[m] + ss*pr;
            vi[m] = cB*vi[m] + ss*pi;
        }
    }

    float U[8];
#define LOADU(g) { _Pragma("unroll") for (int k = 0; k < 8; k++) U[k] = sU[g][k]; }

    // block 0: q0, q4, q7 ; CZ(0,4) CZ(4,7) CZ(7,0)
    LOADU(0); local_u<1>(vr, vi, U);
    LOADU(1); local_u<4>(vr, vi, U);
    LOADU(2); cross_u<1>(vr, vi, t7, U);
#pragma unroll
    for (int m = 0; m < 8; m++) {
        int f = (((m & 1) && (m & 4)) ? 1 : 0)
              ^ (((m & 4) ? t7 : 0))
              ^ (((m & 1) ? t7 : 0));
        if (f) { vr[m] = -vr[m]; vi[m] = -vi[m]; }
    }

    // block 1: q7, q4, q8 ; CZ(7,4) CZ(4,8) CZ(8,7)
    LOADU(3); cross_u<1>(vr, vi, t7, U);
    LOADU(4); local_u<4>(vr, vi, U);
    LOADU(5); cross_u<2>(vr, vi, t8, U);
#pragma unroll
    for (int m = 0; m < 8; m++) {
        int f = (((m & 4) ? t7 : 0))
              ^ (((m & 4) ? t8 : 0))
              ^ (t7 & t8);
        if (f) { vr[m] = -vr[m]; vi[m] = -vi[m]; }
    }

    // block 2: q3, q7, q8 ; CZ(3,7) CZ(7,8) CZ(8,3)
    LOADU(6); local_u<2>(vr, vi, U);
    LOADU(7); cross_u<1>(vr, vi, t7, U);
    LOADU(8); cross_u<2>(vr, vi, t8, U);
#pragma unroll
    for (int m = 0; m < 8; m++) {
        int f = (((m & 2) ? t7 : 0))
              ^ (t7 & t8)
              ^ (((m & 2) ? t8 : 0));
        if (f) { vr[m] = -vr[m]; vi[m] = -vi[m]; }
    }

    // <psi| X_q3 |psi> : q3 is local bit 2
    float ex = 0.f;
#pragma unroll
    for (int m = 0; m < 8; m++) ex += vr[m]*vr[m ^ 2] + vi[m]*vi[m ^ 2];
    ex += __shfl_xor_sync(0xffffffffu, ex, 1);
    ex += __shfl_xor_sync(0xffffffffu, ex, 2);

    // upd MLP: 3 -> 128 (leaky) -> 2, split 32 hidden units per sub-thread
    float u0 = 0.f, u1 = 0.f;
#pragma unroll
    for (int u = 0; u < 32; u++) {
        int j = u * 4 + sub;          // consecutive across sub -> conflict-free
        float h = sb1[j];
        h = fmaf(nf0u, sW1[j], h);
        h = fmaf(nf1u, sW1[128 + j], h);
        h = fmaf(ex,   sW1[256 + j], h);
        h = leaky(h);
        u0 = fmaf(h, sW2[2 * j + 0], u0);
        u1 = fmaf(h, sW2[2 * j + 1], u1);
    }
    u0 += __shfl_xor_sync(0xffffffffu, u0, 1);
    u0 += __shfl_xor_sync(0xffffffffu, u0, 2);
    u1 += __shfl_xor_sync(0xffffffffu, u1, 1);
    u1 += __shfl_xor_sync(0xffffffffu, u1, 2);

    if (sub == 0 && valid) {
        u0 += sb2v[0]; u1 += sb2v[1];
        if (mode == 1) {
            int gi = batch[i];
            atomicAdd(&g_seg[gi * 2 + 0], g_node_f[i * 2 + 0]);
            atomicAdd(&g_seg[gi * 2 + 1], g_node_f[i * 2 + 1]);
            atomicAdd(&g_cnt[gi], 1.f);
            int gt = batch[i0c];
            atomicAdd(&g_seg[gt * 2 + 0], u0);
            atomicAdd(&g_seg[gt * 2 + 1], u1);
        } else {
            g_upd[i * 2 + 0] = u0;
            g_upd[i * 2 + 1] = u1;
        }
    }
}

// multi-hop scatter: node_f[gn[i,0]] += upd[i]
__global__ void k2_scatter(int N, const int* __restrict__ gn)
{
    int i = blockIdx.x * blockDim.x + threadIdx.x;
    if (i >= N) return;
    int t = max(gn[i * 4], 0);
    atomicAdd(&g_node_f[t * 2 + 0], g_upd[i * 2 + 0]);
    atomicAdd(&g_node_f[t * 2 + 1], g_upd[i * 2 + 1]);
}

// multi-hop final segment sums
__global__ void k_seg(int N, const int* __restrict__ batch)
{
    int i = blockIdx.x * blockDim.x + threadIdx.x;
    if (i >= N) return;
    int g = batch[i];
    atomicAdd(&g_seg[g * 2 + 0], g_node_f[i * 2 + 0]);
    atomicAdd(&g_seg[g * 2 + 1], g_node_f[i * 2 + 1]);
    atomicAdd(&g_cnt[g], 1.f);
}

// ---------------- K3: per-graph mean + head MLP ---------------------------
__global__ void k3_head(int G,
                        const float* __restrict__ hW1, const float* __restrict__ hb1,
                        const float* __restrict__ hW2, const float* __restrict__ hb2,
                        float* __restrict__ out)
{
    int g = blockIdx.x * blockDim.x + threadIdx.x;
    if (g >= G) return;
    float c = g_cnt[g];
    float inv = (c > 0.f) ? (1.f / c) : 0.f;
    float e0 = g_seg[g * 2 + 0] * inv;
    float e1 = g_seg[g * 2 + 1] * inv;
    float h0 = leaky(e0 * hW1[0] + e1 * hW1[2] + hb1[0]);
    float h1 = leaky(e0 * hW1[1] + e1 * hW1[3] + hb1[1]);
    out[g * 2 + 0] = h0 * hW2[0] + h1 * hW2[2] + hb2[0];
    out[g * 2 + 1] = h0 * hW2[1] + h1 * hW2[3] + hb2[1];
}

extern "C" void kernel_launch(void* const* d_in, const int* in_sizes, int n_in,
                              void* d_out, int out_size)
{
    const float* node_feat = (const float*)d_in[0];
    const float* edge_attr = (const float*)d_in[1];
    const float* nW1 = (const float*)d_in[2];
    const float* nb1 = (const float*)d_in[3];
    const float* nW2 = (const float*)d_in[4];
    const float* nb2 = (const float*)d_in[5];
    const float* eW1 = (const float*)d_in[6];
    const float* eb1 = (const float*)d_in[7];
    const float* eW2 = (const float*)d_in[8];
    const float* eb2 = (const float*)d_in[9];
    const float* theta = (const float*)d_in[10];
    const float* uW1 = (const float*)d_in[11];
    const float* ub1 = (const float*)d_in[12];
    const float* uW2 = (const float*)d_in[13];
    const float* ub2 = (const float*)d_in[14];
    const float* hW1 = (const float*)d_in[15];
    const float* hb1 = (const float*)d_in[16];
    const float* hW2 = (const float*)d_in[17];
    const float* hb2 = (const float*)d_in[18];
    const int* gn = (const int*)d_in[19];
    const int* ge = (const int*)d_in[20];
    const int* batch = (const int*)d_in[21];

    int N = in_sizes[0] / 16;
    int H = in_sizes[10] / 27;
    int G = out_size / 2;

    // k1: warp per row
    int nb1blocks = (N + 3) / 4;
    k1_feat<<<nb1blocks, 128>>>(node_feat, N, edge_attr, nW1, nb1, nW2, nb2,
                                eW1, eb1, eW2, eb2, ge);

    // k2: 4 threads per row, 16 rows per 64-thread block
    int nb2blocks = (N + 15) / 16;
    if (H == 1) {
        k2_pqc<<<nb2blocks, 64>>>(N, 1, theta, uW1, ub1, uW2, ub2, gn, batch);
    } else {
        const int T = 128;
        int nbs = (N + T - 1) / T;
        for (int h = 0; h < H; h++) {
            k2_pqc<<<nb2blocks, 64>>>(N, 0, theta + 27 * h,
                                      uW1 + 384 * h, ub1 + 128 * h,
                                      uW2 + 256 * h, ub2 + 2 * h, gn, batch);
            k2_scatter<<<nbs, T>>>(N, gn);
        }
        k_seg<<<nbs, T>>>(N, batch);
    }

    k3_head<<<(G + 127) / 128, 128>>>(G, hW1, hb1, hW2, hb2, (float*)d_out);
}

// round 4
// speedup vs baseline: 1.2196x; 1.0165x over previous
#include <cuda_runtime.h>
#include <math.h>

#define NMAX 16384
#define GMAX 1024
#define PI_F 3.14159265358979323846f

__device__ float g_node_f[NMAX * 2];
__device__ float g_eAB[NMAX * 2];
__device__ float g_upd[NMAX * 2];
__device__ float g_seg[GMAX * 2];
__device__ float g_cnt[GMAX];
__device__ int   g_ctr;

__device__ __forceinline__ float leaky(float x) { return x > 0.f ? x : 0.2f * x; }

__device__ __forceinline__ float ldcg(const float* p) {
    float v; asm volatile("ld.global.cg.f32 %0, [%1];" : "=f"(v) : "l"(p)); return v;
}

// ---------------- K1: 4 rows per warp, weights register-resident (scalar loads)
// lane handles hidden units j = 4*lane .. 4*lane+3
__global__ void k1_feat(const float* __restrict__ node_feat, int N,
                        const float* __restrict__ edge_attr,
                        const float* __restrict__ nW1, const float* __restrict__ nb1,
                        const float* __restrict__ nW2, const float* __restrict__ nb2,
                        const float* __restrict__ eW1, const float* __restrict__ eb1,
                        const float* __restrict__ eW2, const float* __restrict__ eb2,
                        const int* __restrict__ ge)
{
    int tid = threadIdx.x;
    int lane = tid & 31;
    int w = tid >> 5;
    int gtid = blockIdx.x * blockDim.x + tid;

    if (gtid < GMAX * 2) g_seg[gtid] = 0.f;
    else if (gtid < GMAX * 3) g_cnt[gtid - GMAX * 2] = 0.f;
    if (gtid == 0) g_ctr = 0;

    int j0 = 4 * lane;

    float wn[16][4];
#pragma unroll
    for (int k = 0; k < 16; k++) {
#pragma unroll
        for (int q = 0; q < 4; q++) wn[k][q] = __ldg(nW1 + k * 128 + j0 + q);
    }
    float bn[4], n2[4][2];
#pragma unroll
    for (int q = 0; q < 4; q++) {
        bn[q] = __ldg(nb1 + j0 + q);
        n2[q][0] = __ldg(nW2 + 2 * (j0 + q) + 0);
        n2[q][1] = __ldg(nW2 + 2 * (j0 + q) + 1);
    }
    float we[8][4];
#pragma unroll
    for (int k = 0; k < 8; k++) {
#pragma unroll
        for (int q = 0; q < 4; q++) we[k][q] = __ldg(eW1 + k * 128 + j0 + q);
    }
    float be[4], e2[4][2];
#pragma unroll
    for (int q = 0; q < 4; q++) {
        be[q] = __ldg(eb1 + j0 + q);
        e2[q][0] = __ldg(eW2 + 2 * (j0 + q) + 0);
        e2[q][1] = __ldg(eW2 + 2 * (j0 + q) + 1);
    }
    float nb2x = __ldg(nb2 + 0), nb2y = __ldg(nb2 + 1);
    float eb2x = __ldg(eb2 + 0), eb2y = __ldg(eb2 + 1);

    int warpId = blockIdx.x * (blockDim.x >> 5) + w;
    int base = warpId * 4;

#pragma unroll
    for (int rr = 0; rr < 4; rr++) {
        int row = base + rr;
        bool valid = row < N;
        int ic = min(row, N - 1);

        float x[16];
#pragma unroll
        for (int k = 0; k < 16; k++) x[k] = __ldg(node_feat + ic * 16 + k);

        float h[4] = {bn[0], bn[1], bn[2], bn[3]};
#pragma unroll
        for (int k = 0; k < 16; k++) {
#pragma unroll
            for (int q = 0; q < 4; q++) h[q] = fmaf(x[k], wn[k][q], h[q]);
        }
        float o0 = 0.f, o1 = 0.f;
#pragma unroll
        for (int q = 0; q < 4; q++) {
            float hq = leaky(h[q]);
            o0 = fmaf(hq, n2[q][0], o0);
            o1 = fmaf(hq, n2[q][1], o1);
        }

        int eidx = __ldg(ge + ic * 3);
        int ec = max(eidx, 0);
        float y[8];
#pragma unroll
        for (int k = 0; k < 8; k++) y[k] = __ldg(edge_attr + ec * 8 + k);

        float g[4] = {be[0], be[1], be[2], be[3]};
#pragma unroll
        for (int k = 0; k < 8; k++) {
#pragma unroll
            for (int q = 0; q < 4; q++) g[q] = fmaf(y[k], we[k][q], g[q]);
        }
        float p0 = 0.f, p1 = 0.f;
#pragma unroll
        for (int q = 0; q < 4; q++) {
            float gq = leaky(g[q]);
            p0 = fmaf(gq, e2[q][0], p0);
            p1 = fmaf(gq, e2[q][1], p1);
        }

#pragma unroll
        for (int off = 16; off >= 1; off >>= 1) {
            o0 += __shfl_xor_sync(0xffffffffu, o0, off);
            o1 += __shfl_xor_sync(0xffffffffu, o1, off);
            p0 += __shfl_xor_sync(0xffffffffu, p0, off);
            p1 += __shfl_xor_sync(0xffffffffu, p1, off);
        }

        if (lane == 0 && valid) {
            g_node_f[row * 2 + 0] = tanhf(o0 + nb2x) * PI_F;
            g_node_f[row * 2 + 1] = tanhf(o1 + nb2y) * PI_F;
            g_eAB[row * 2 + 0] = (eidx >= 0) ? tanhf(p0 + eb2x) * PI_F : 0.f;
            g_eAB[row * 2 + 1] = (eidx >= 0) ? tanhf(p1 + eb2y) * PI_F : 0.f;
        }
    }
}

// ---------------- K2: halved PQC (16-amp chi), 2 threads/row ----------------
// chi over (q0,q4,q7,q8); local bits: q0=1, q4=2, q8=4; q7 = lane bit (xor 1).
// <X_q3> = 2*Re(conj(a0)*a1) * <chi| M7 (x) M8 |chi>, M = U^dag Z U (theta-only).

__device__ __forceinline__ void u_pair(float& lr, float& li, float& hr, float& hi,
                                       const float* U) {
    float nlr = U[0]*lr - U[1]*li + U[2]*hr - U[3]*hi;
    float nli = U[0]*li + U[1]*lr + U[2]*hi + U[3]*hr;
    float nhr = U[4]*lr - U[5]*li + U[6]*hr - U[7]*hi;
    float nhi = U[4]*li + U[5]*lr + U[6]*hi + U[7]*hr;
    lr = nlr; li = nli; hr = nhr; hi = nhi;
}

__global__ void k2_pqc(int N, int mode, int G,
                       const float* __restrict__ theta,
                       const float* __restrict__ uW1, const float* __restrict__ ub1,
                       const float* __restrict__ uW2, const float* __restrict__ ub2,
                       const int* __restrict__ gn, const int* __restrict__ batch,
                       const float* __restrict__ hW1, const float* __restrict__ hb1,
                       const float* __restrict__ hW2, const float* __restrict__ hb2,
                       float* __restrict__ out)
{
    __shared__ float sU[7][8];
    __shared__ float sM[6];                 // d7,k7r,k7i, d8,k8r,k8i
    __shared__ float sW1[384], sb1[128], sW2[256], sb2v[2];
    __shared__ int s_last;
    int tid = threadIdx.x;

    if (tid < 9) {
        int g = tid;
        float sx, cx, sy, cy, sz, cz;
        sincosf(0.5f * theta[3 * g + 0], &sx, &cx);
        sincosf(0.5f * theta[3 * g + 1], &sy, &cy);
        sincosf(0.5f * theta[3 * g + 2], &sz, &cz);
        float M00r =  cy*cx, M00i =  sy*sx;
        float M01r = -sy*cx, M01i = -cy*sx;
        float M10r =  sy*cx, M10i = -cy*sx;
        float M11r =  cy*cx, M11i = -sy*sx;
        float u[8];
        u[0] = cz*M00r + sz*M00i;  u[1] = cz*M00i - sz*M00r;
        u[2] = cz*M01r + sz*M01i;  u[3] = cz*M01i - sz*M01r;
        u[4] = cz*M10r - sz*M10i;  u[5] = cz*M10i + sz*M10r;
        u[6] = cz*M11r - sz*M11i;  u[7] = cz*M11i + sz*M11r;
        if (g < 7) {
#pragma unroll
            for (int k = 0; k < 8; k++) sU[g][k] = u[k];
        } else {
            int off = (g == 7) ? 0 : 3;
            sM[off + 0] = u[0]*u[0] + u[1]*u[1] - (u[4]*u[4] + u[5]*u[5]);
            sM[off + 1] = u[0]*u[2] + u[1]*u[3] - (u[4]*u[6] + u[5]*u[7]);
            sM[off + 2] = u[0]*u[3] - u[1]*u[2] - (u[4]*u[7] - u[5]*u[6]);
        }
    }
    for (int j = tid; j < 384; j += blockDim.x) sW1[j] = __ldg(uW1 + j);
    for (int j = tid; j < 128; j += blockDim.x) sb1[j] = __ldg(ub1 + j);
    for (int j = tid; j < 256; j += blockDim.x) sW2[j] = __ldg(uW2 + j);
    if (tid < 2) sb2v[tid] = ub2[tid];
    __syncthreads();

    int row = blockIdx.x * (blockDim.x >> 1) + (tid >> 1);
    int t7 = tid & 1;
    int i = min(row, N - 1);
    bool valid = row < N;

    int i0 = __ldg(gn + i * 4 + 0), i1 = __ldg(gn + i * 4 + 1);
    int i0c = max(i0, 0), i1c = max(i1, 0);
    float nf0u = g_node_f[i0c * 2 + 0];
    float nf1u = g_node_f[i0c * 2 + 1];
    float nA0 = (i0 >= 0) ? nf0u : 0.f;
    float nA1 = (i0 >= 0) ? nf1u : 0.f;
    float nB0 = (i1 >= 0) ? g_node_f[i1c * 2 + 0] : 0.f;
    float nB1 = (i1 >= 0) ? g_node_f[i1c * 2 + 1] : 0.f;
    float eA = g_eAB[i * 2 + 0], eB = g_eAB[i * 2 + 1];

    float cA, sA, cB, sB, c3a, s3a, c3b, s3b, c4a, s4a, c4b, s4b;
    __sincosf(0.5f * eA,  &sA,  &cA);
    __sincosf(0.5f * eB,  &sB,  &cB);
    __sincosf(0.5f * nA0, &s3a, &c3a);
    __sincosf(0.5f * nA1, &s3b, &c3b);
    __sincosf(0.5f * nB0, &s4a, &c4a);
    __sincosf(0.5f * nB1, &s4b, &c4b);

    // init product (q0, q4); q7=q8=|0>, so only t7==0 lane nonzero, amps 0..3
    float f0r[2], f0i[2], f4r[2], f4i[2];
    f0r[0] = cA*cB;   f0i[0] = -cA*sB;   f0r[1] = sA*cB;   f0i[1] = sA*sB;
    f4r[0] = c4a*c4b; f4i[0] = -c4a*s4b; f4r[1] = s4a*c4b; f4i[1] = s4a*s4b;

    float msk = (t7 == 0) ? 1.f : 0.f;
    float vr[8], vi[8];
#pragma unroll
    for (int m = 0; m < 8; m++) {
        if (m < 4) {
            int b0 = m & 1, b1 = (m >> 1) & 1;
            vr[m] = msk * (f0r[b0]*f4r[b1] - f0i[b0]*f4i[b1]);
            vi[m] = msk * (f0r[b0]*f4i[b1] + f0i[b0]*f4r[b1]);
        } else { vr[m] = 0.f; vi[m] = 0.f; }
    }

    // CRX(nB0): c=q4(bit1), t=q7(lane)
#pragma unroll
    for (int m = 0; m < 8; m++) if (m & 2) {
        float pr = __shfl_xor_sync(0xffffffffu, vr[m], 1);
        float pi = __shfl_xor_sync(0xffffffffu, vi[m], 1);
        float nr = c4a*vr[m] + s4a*pi;
        float ni = c4a*vi[m] - s4a*pr;
        vr[m] = nr; vi[m] = ni;
    }
    // CRY(eA): c=q0(bit0), t=q7
    {
        float ss = t7 ? sA : -sA;
#pragma unroll
        for (int m = 0; m < 8; m++) if (m & 1) {
            float pr = __shfl_xor_sync(0xffffffffu, vr[m], 1);
            float pi = __shfl_xor_sync(0xffffffffu, vi[m], 1);
            vr[m] = cA*vr[m] + ss*pr;
            vi[m] = cA*vi[m] + ss*pi;
        }
    }
    // CRZ(nB1): c=q4, t=q8(bit2) — local diagonal
#pragma unroll
    for (int m = 0; m < 8; m++) if (m & 2) {
        float r = vr[m], ii = vi[m];
        if (m & 4) { vr[m] = c4b*r - s4b*ii; vi[m] = c4b*ii + s4b*r; }
        else       { vr[m] = c4b*r + s4b*ii; vi[m] = c4b*ii - s4b*r; }
    }
    // CRY(eB): c=q0, t=q8 — local pairs (m, m|4), m in {1,3}
#pragma unroll
    for (int m = 1; m < 4; m += 2) {
        float lr = vr[m], li = vi[m], hr = vr[m+4], hi = vi[m+4];
        vr[m]   = cB*lr - sB*hr;  vi[m]   = cB*li - sB*hi;
        vr[m+4] = sB*lr + cB*hr;  vi[m+4] = sB*li + cB*hi;
    }

    float U[8];
#define LOADU(g) { _Pragma("unroll") for (int k = 0; k < 8; k++) U[k] = sU[g][k]; }
#define CROSSU() { \
    float Cmr = t7 ? U[6] : U[0], Cmi = t7 ? U[7] : U[1]; \
    float Cpr = t7 ? U[4] : U[2], Cpi = t7 ? U[5] : U[3]; \
    _Pragma("unroll") \
    for (int m = 0; m < 8; m++) { \
        float pr = __shfl_xor_sync(0xffffffffu, vr[m], 1); \
        float pi = __shfl_xor_sync(0xffffffffu, vi[m], 1); \
        float nr = Cmr*vr[m] - Cmi*vi[m] + Cpr*pr - Cpi*pi; \
        float ni = Cmr*vi[m] + Cmi*vr[m] + Cpr*pi + Cpi*pr; \
        vr[m] = nr; vi[m] = ni; \
    } }

    // Block 0: U0 on q0, U1 on q4, U2 on q7; CZ(0,4) CZ(4,7) CZ(7,0)
    LOADU(0);
    u_pair(vr[0], vi[0], vr[1], vi[1], U);
    u_pair(vr[2], vi[2], vr[3], vi[3], U);
    u_pair(vr[4], vi[4], vr[5], vi[5], U);
    u_pair(vr[6], vi[6], vr[7], vi[7], U);
    LOADU(1);
    u_pair(vr[0], vi[0], vr[2], vi[2], U);
    u_pair(vr[1], vi[1], vr[3], vi[3], U);
    u_pair(vr[4], vi[4], vr[6], vi[6], U);
    u_pair(vr[5], vi[5], vr[7], vi[7], U);
    LOADU(2); CROSSU();
#pragma unroll
    for (int m = 0; m < 8; m++) {
        int f = (((m & 1) && (m & 2)) ? 1 : 0) ^ (((m & 2) && t7) ? 1 : 0)
              ^ (((m & 1) && t7) ? 1 : 0);
        if (f) { vr[m] = -vr[m]; vi[m] = -vi[m]; }
    }

    // Block 1: U3 on q7, U4 on q4, U5 on q8; CZ(7,4) CZ(4,8) CZ(8,7)
    LOADU(3); CROSSU();
    LOADU(4);
    u_pair(vr[0], vi[0], vr[2], vi[2], U);
    u_pair(vr[1], vi[1], vr[3], vi[3], U);
    u_pair(vr[4], vi[4], vr[6], vi[6], U);
    u_pair(vr[5], vi[5], vr[7], vi[7], U);
    LOADU(5);
    u_pair(vr[0], vi[0], vr[4], vi[4], U);
    u_pair(vr[1], vi[1], vr[5], vi[5], U);
    u_pair(vr[2], vi[2], vr[6], vi[6], U);
    u_pair(vr[3], vi[3], vr[7], vi[7], U);
#pragma unroll
    for (int m = 0; m < 8; m++) {
        int f = (((m & 2) && t7) ? 1 : 0) ^ (((m & 2) && (m & 4)) ? 1 : 0)
              ^ (((m & 4) && t7) ? 1 : 0);
        if (f) { vr[m] = -vr[m]; vi[m] = -vi[m]; }
    }

    // Observable: S = <chi| M7 (x) M8 |chi>
    float d7 = sM[0], k7r = sM[1], k7i = sM[2];
    float d8 = sM[3], k8r = sM[4], k8i = sM[5];
    float ur[8], ui[8];
#pragma unroll
    for (int m = 0; m < 4; m++) {
        ur[m]   = d8*vr[m] + k8r*vr[m+4] - k8i*vi[m+4];
        ui[m]   = d8*vi[m] + k8r*vi[m+4] + k8i*vr[m+4];
        ur[m+4] = k8r*vr[m] + k8i*vi[m] - d8*vr[m+4];
        ui[m+4] = k8r*vi[m] - k8i*vr[m] - d8*vi[m+4];
    }
    float d7s = t7 ? -d7 : d7;
    float Cr = k7r, Ci = t7 ? -k7i : k7i;
    float S = 0.f;
#pragma unroll
    for (int m = 0; m < 8; m++) {
        float upr = __shfl_xor_sync(0xffffffffu, ur[m], 1);
        float upi = __shfl_xor_sync(0xffffffffu, ui[m], 1);
        S += d7s * (vr[m]*ur[m] + vi[m]*ui[m]);
        float Apart = vr[m]*upr + vi[m]*upi;
        float Bpart = vr[m]*upi - vi[m]*upr;
        S += Cr*Apart - Ci*Bpart;
    }
    S += __shfl_xor_sync(0xffffffffu, S, 1);

    // q3 scalar: a = U6 * (RZ(nA1) RY(nA0) |0>), w2 = 2 Re(conj(a0) a1)
    LOADU(6);
    {
        float p0r = c3a*c3b, p0i = -c3a*s3b, p1r = s3a*c3b, p1i = s3a*s3b;
        float a0r = U[0]*p0r - U[1]*p0i + U[2]*p1r - U[3]*p1i;
        float a0i = U[0]*p0i + U[1]*p0r + U[2]*p1i + U[3]*p1r;
        float a1r = U[4]*p0r - U[5]*p0i + U[6]*p1r - U[7]*p1i;
        float a1i = U[4]*p0i + U[5]*p0r + U[6]*p1i + U[7]*p1r;
        S *= 2.f * (a0r*a1r + a0i*a1i);
    }
    float ex = S;

    // upd MLP: 3 -> 128 (leaky) -> 2, hidden split j = 2u + t7
    float acc0 = 0.f, acc1 = 0.f;
#pragma unroll 16
    for (int u = 0; u < 64; u++) {
        int j = 2*u + t7;
        float h = sb1[j];
        h = fmaf(nf0u, sW1[j], h);
        h = fmaf(nf1u, sW1[128 + j], h);
        h = fmaf(ex,   sW1[256 + j], h);
        h = leaky(h);
        acc0 = fmaf(h, sW2[2*j + 0], acc0);
        acc1 = fmaf(h, sW2[2*j + 1], acc1);
    }
    acc0 += __shfl_xor_sync(0xffffffffu, acc0, 1);
    acc1 += __shfl_xor_sync(0xffffffffu, acc1, 1);

    if (t7 == 0 && valid) {
        acc0 += sb2v[0]; acc1 += sb2v[1];
        if (mode == 1) {
            int gi = batch[i];
            atomicAdd(&g_seg[gi * 2 + 0], g_node_f[i * 2 + 0]);
            atomicAdd(&g_seg[gi * 2 + 1], g_node_f[i * 2 + 1]);
            atomicAdd(&g_cnt[gi], 1.f);
            int gt = batch[i0c];
            atomicAdd(&g_seg[gt * 2 + 0], acc0);
            atomicAdd(&g_seg[gt * 2 + 1], acc1);
        } else {
            g_upd[i * 2 + 0] = acc0;
            g_upd[i * 2 + 1] = acc1;
        }
    }

    // fused head: last block to finish computes the output
    if (mode == 1) {
        __threadfence();
        __syncthreads();
        if (tid == 0) s_last = (atomicAdd(&g_ctr, 1) == (int)gridDim.x - 1) ? 1 : 0;
        __syncthreads();
        if (s_last) {
            for (int g = tid; g < G; g += blockDim.x) {
                float c = ldcg(&g_cnt[g]);
                float inv = (c > 0.f) ? (1.f / c) : 0.f;
                float e0 = ldcg(&g_seg[g * 2 + 0]) * inv;
                float e1 = ldcg(&g_seg[g * 2 + 1]) * inv;
                float h0 = leaky(e0 * hW1[0] + e1 * hW1[2] + hb1[0]);
                float h1 = leaky(e0 * hW1[1] + e1 * hW1[3] + hb1[1]);
                out[g * 2 + 0] = h0 * hW2[0] + h1 * hW2[2] + hb2[0];
                out[g * 2 + 1] = h0 * hW2[1] + h1 * hW2[3] + hb2[1];
            }
        }
    }
}

// ---------------- multi-hop helpers (H > 1 only) ----------------------------
__global__ void k2_scatter(int N, const int* __restrict__ gn)
{
    int i = blockIdx.x * blockDim.x + threadIdx.x;
    if (i >= N) return;
    int t = max(gn[i * 4], 0);
    atomicAdd(&g_node_f[t * 2 + 0], g_upd[i * 2 + 0]);
    atomicAdd(&g_node_f[t * 2 + 1], g_upd[i * 2 + 1]);
}

__global__ void k_seg(int N, const int* __restrict__ batch)
{
    int i = blockIdx.x * blockDim.x + threadIdx.x;
    if (i >= N) return;
    int g = batch[i];
    atomicAdd(&g_seg[g * 2 + 0], g_node_f[i * 2 + 0]);
    atomicAdd(&g_seg[g * 2 + 1], g_node_f[i * 2 + 1]);
    atomicAdd(&g_cnt[g], 1.f);
}

__global__ void k3_head(int G,
                        const float* __restrict__ hW1, const float* __restrict__ hb1,
                        const float* __restrict__ hW2, const float* __restrict__ hb2,
                        float* __restrict__ out)
{
    int g = blockIdx.x * blockDim.x + threadIdx.x;
    if (g >= G) return;
    float c = g_cnt[g];
    float inv = (c > 0.f) ? (1.f / c) : 0.f;
    float e0 = g_seg[g * 2 + 0] * inv;
    float e1 = g_seg[g * 2 + 1] * inv;
    float h0 = leaky(e0 * hW1[0] + e1 * hW1[2] + hb1[0]);
    float h1 = leaky(e0 * hW1[1] + e1 * hW1[3] + hb1[1]);
    out[g * 2 + 0] = h0 * hW2[0] + h1 * hW2[2] + hb2[0];
    out[g * 2 + 1] = h0 * hW2[1] + h1 * hW2[3] + hb2[1];
}

extern "C" void kernel_launch(void* const* d_in, const int* in_sizes, int n_in,
                              void* d_out, int out_size)
{
    const float* node_feat = (const float*)d_in[0];
    const float* edge_attr = (const float*)d_in[1];
    const float* nW1 = (const float*)d_in[2];
    const float* nb1 = (const float*)d_in[3];
    const float* nW2 = (const float*)d_in[4];
    const float* nb2 = (const float*)d_in[5];
    const float* eW1 = (const float*)d_in[6];
    const float* eb1 = (const float*)d_in[7];
    const float* eW2 = (const float*)d_in[8];
    const float* eb2 = (const float*)d_in[9];
    const float* theta = (const float*)d_in[10];
    const float* uW1 = (const float*)d_in[11];
    const float* ub1 = (const float*)d_in[12];
    const float* uW2 = (const float*)d_in[13];
    const float* ub2 = (const float*)d_in[14];
    const float* hW1 = (const float*)d_in[15];
    const float* hb1 = (const float*)d_in[16];
    const float* hW2 = (const float*)d_in[17];
    const float* hb2 = (const float*)d_in[18];
    const int* gn = (const int*)d_in[19];
    const int* ge = (const int*)d_in[20];
    const int* batch = (const int*)d_in[21];

    int N = in_sizes[0] / 16;
    int H = in_sizes[10] / 27;
    int G = out_size / 2;

    // k1: 4 rows per warp, 4 warps per block -> 16 rows per block
    int k1blocks = (N + 15) / 16;
    k1_feat<<<k1blocks, 128>>>(node_feat, N, edge_attr, nW1, nb1, nW2, nb2,
                               eW1, eb1, eW2, eb2, ge);

    // k2: 2 threads/row, 64-thread blocks -> 32 rows per block
    int k2blocks = (N + 31) / 32;
    if (H == 1) {
        k2_pqc<<<k2blocks, 64>>>(N, 1, G, theta, uW1, ub1, uW2, ub2, gn, batch,
                                 hW1, hb1, hW2, hb2, (float*)d_out);
    } else {
        const int T = 128;
        int nbs = (N + T - 1) / T;
        for (int h = 0; h < H; h++) {
            k2_pqc<<<k2blocks, 64>>>(N, 0, G, theta + 27 * h,
                                     uW1 + 384 * h, ub1 + 128 * h,
                                     uW2 + 256 * h, ub2 + 2 * h, gn, batch,
                                     hW1, hb1, hW2, hb2, (float*)d_out);
            k2_scatter<<<nbs, T>>>(N, gn);
        }
        k_seg<<<nbs, T>>>(N, batch);
        k3_head<<<(G + 127) / 128, 128>>>(G, hW1, hb1, hW2, hb2, (float*)d_out);
    }
}

// round 6
// speedup vs baseline: 1.2635x; 1.0360x over previous
#include <cuda_runtime.h>
#include <math.h>

#define NMAX 16384
#define GMAX 1024
#define PI_F 3.14159265358979323846f

__device__ float g_node_f[NMAX * 2];
__device__ float g_eAB[NMAX * 2];
__device__ float g_upd[NMAX * 2];
__device__ float g_seg[GMAX * 2];
__device__ float g_cnt[GMAX];
__device__ int   g_ctr;

__device__ __forceinline__ float leaky(float x) { return x > 0.f ? x : 0.2f * x; }

__device__ __forceinline__ float ldcg(const float* p) {
    float v; asm volatile("ld.global.cg.f32 %0, [%1];" : "=f"(v) : "l"(p)); return v;
}

// ---------------- K1: 4 rows per warp, weights register-resident (scalar loads)
__global__ void k1_feat(const float* __restrict__ node_feat, int N,
                        const float* __restrict__ edge_attr,
                        const float* __restrict__ nW1, const float* __restrict__ nb1,
                        const float* __restrict__ nW2, const float* __restrict__ nb2,
                        const float* __restrict__ eW1, const float* __restrict__ eb1,
                        const float* __restrict__ eW2, const float* __restrict__ eb2,
                        const int* __restrict__ ge)
{
    int tid = threadIdx.x;
    int lane = tid & 31;
    int w = tid >> 5;
    int gtid = blockIdx.x * blockDim.x + tid;

    if (gtid < GMAX * 2) g_seg[gtid] = 0.f;
    else if (gtid < GMAX * 3) g_cnt[gtid - GMAX * 2] = 0.f;
    if (gtid == 0) g_ctr = 0;

    int j0 = 4 * lane;

    float wn[16][4];
#pragma unroll
    for (int k = 0; k < 16; k++) {
#pragma unroll
        for (int q = 0; q < 4; q++) wn[k][q] = __ldg(nW1 + k * 128 + j0 + q);
    }
    float bn[4], n2[4][2];
#pragma unroll
    for (int q = 0; q < 4; q++) {
        bn[q] = __ldg(nb1 + j0 + q);
        n2[q][0] = __ldg(nW2 + 2 * (j0 + q) + 0);
        n2[q][1] = __ldg(nW2 + 2 * (j0 + q) + 1);
    }
    float we[8][4];
#pragma unroll
    for (int k = 0; k < 8; k++) {
#pragma unroll
        for (int q = 0; q < 4; q++) we[k][q] = __ldg(eW1 + k * 128 + j0 + q);
    }
    float be[4], e2[4][2];
#pragma unroll
    for (int q = 0; q < 4; q++) {
        be[q] = __ldg(eb1 + j0 + q);
        e2[q][0] = __ldg(eW2 + 2 * (j0 + q) + 0);
        e2[q][1] = __ldg(eW2 + 2 * (j0 + q) + 1);
    }
    float nb2x = __ldg(nb2 + 0), nb2y = __ldg(nb2 + 1);
    float eb2x = __ldg(eb2 + 0), eb2y = __ldg(eb2 + 1);

    int warpId = blockIdx.x * (blockDim.x >> 5) + w;
    int base = warpId * 4;

#pragma unroll
    for (int rr = 0; rr < 4; rr++) {
        int row = base + rr;
        bool valid = row < N;
        int ic = min(row, N - 1);

        float x[16];
#pragma unroll
        for (int k = 0; k < 16; k++) x[k] = __ldg(node_feat + ic * 16 + k);

        float h[4] = {bn[0], bn[1], bn[2], bn[3]};
#pragma unroll
        for (int k = 0; k < 16; k++) {
#pragma unroll
            for (int q = 0; q < 4; q++) h[q] = fmaf(x[k], wn[k][q], h[q]);
        }
        float o0 = 0.f, o1 = 0.f;
#pragma unroll
        for (int q = 0; q < 4; q++) {
            float hq = leaky(h[q]);
            o0 = fmaf(hq, n2[q][0], o0);
            o1 = fmaf(hq, n2[q][1], o1);
        }

        int eidx = __ldg(ge + ic * 3);
        int ec = max(eidx, 0);
        float y[8];
#pragma unroll
        for (int k = 0; k < 8; k++) y[k] = __ldg(edge_attr + ec * 8 + k);

        float g[4] = {be[0], be[1], be[2], be[3]};
#pragma unroll
        for (int k = 0; k < 8; k++) {
#pragma unroll
            for (int q = 0; q < 4; q++) g[q] = fmaf(y[k], we[k][q], g[q]);
        }
        float p0 = 0.f, p1 = 0.f;
#pragma unroll
        for (int q = 0; q < 4; q++) {
            float gq = leaky(g[q]);
            p0 = fmaf(gq, e2[q][0], p0);
            p1 = fmaf(gq, e2[q][1], p1);
        }

#pragma unroll
        for (int off = 16; off >= 1; off >>= 1) {
            o0 += __shfl_xor_sync(0xffffffffu, o0, off);
            o1 += __shfl_xor_sync(0xffffffffu, o1, off);
            p0 += __shfl_xor_sync(0xffffffffu, p0, off);
            p1 += __shfl_xor_sync(0xffffffffu, p1, off);
        }

        if (lane == 0 && valid) {
            g_node_f[row * 2 + 0] = tanhf(o0 + nb2x) * PI_F;
            g_node_f[row * 2 + 1] = tanhf(o1 + nb2y) * PI_F;
            g_eAB[row * 2 + 0] = (eidx >= 0) ? tanhf(p0 + eb2x) * PI_F : 0.f;
            g_eAB[row * 2 + 1] = (eidx >= 0) ? tanhf(p1 + eb2y) * PI_F : 0.f;
        }
    }
}

// ---------------- K2: one thread per row, full 16-amp chi in registers -------
// chi over (q0,q4,q7,q8); bits: q0=1, q4=2, q7=4, q8=8. No shuffles.
// <X_q3> = 2*Re(conj(a0)*a1) * <chi| M7 (x) M8 |chi>, M = U^dag Z U.

__global__ void __launch_bounds__(64)
k2_pqc(int N, int mode, int G,
       const float* __restrict__ theta,
       const float* __restrict__ uW1, const float* __restrict__ ub1,
       const float* __restrict__ uW2, const float* __restrict__ ub2,
       const int* __restrict__ gn, const int* __restrict__ batch,
       const float* __restrict__ hW1, const float* __restrict__ hb1,
       const float* __restrict__ hW2, const float* __restrict__ hb2,
       float* __restrict__ out)
{
    __shared__ float sU[7][8];
    __shared__ float sM[6];                 // d7,k7r,k7i, d8,k8r,k8i
    __shared__ float4 sP1[128];             // {W1_0j, W1_1j, W1_2j, b1_j}
    __shared__ float2 sP2[128];             // {W2_j0, W2_j1}
    __shared__ float sb2v[2];
    __shared__ int s_last;
    int tid = threadIdx.x;

    if (tid < 9) {
        int g = tid;
        float sx, cx, sy, cy, sz, cz;
        sincosf(0.5f * theta[3 * g + 0], &sx, &cx);
        sincosf(0.5f * theta[3 * g + 1], &sy, &cy);
        sincosf(0.5f * theta[3 * g + 2], &sz, &cz);
        float M00r =  cy*cx, M00i =  sy*sx;
        float M01r = -sy*cx, M01i = -cy*sx;
        float M10r =  sy*cx, M10i = -cy*sx;
        float M11r =  cy*cx, M11i = -sy*sx;
        float u[8];
        u[0] = cz*M00r + sz*M00i;  u[1] = cz*M00i - sz*M00r;
        u[2] = cz*M01r + sz*M01i;  u[3] = cz*M01i - sz*M01r;
        u[4] = cz*M10r - sz*M10i;  u[5] = cz*M10i + sz*M10r;
        u[6] = cz*M11r - sz*M11i;  u[7] = cz*M11i + sz*M11r;
        if (g < 7) {
#pragma unroll
            for (int k = 0; k < 8; k++) sU[g][k] = u[k];
        } else {
            int off = (g == 7) ? 0 : 3;
            sM[off + 0] = u[0]*u[0] + u[1]*u[1] - (u[4]*u[4] + u[5]*u[5]);
            sM[off + 1] = u[0]*u[2] + u[1]*u[3] - (u[4]*u[6] + u[5]*u[7]);
            sM[off + 2] = u[0]*u[3] - u[1]*u[2] - (u[4]*u[7] - u[5]*u[6]);
        }
    }
    for (int j = tid; j < 128; j += blockDim.x) {
        sP1[j] = make_float4(__ldg(uW1 + j), __ldg(uW1 + 128 + j),
                             __ldg(uW1 + 256 + j), __ldg(ub1 + j));
        sP2[j] = make_float2(__ldg(uW2 + 2*j + 0), __ldg(uW2 + 2*j + 1));
    }
    if (tid < 2) sb2v[tid] = ub2[tid];
    __syncthreads();

    int row = blockIdx.x * blockDim.x + tid;
    int i = min(row, N - 1);
    bool valid = row < N;

    int i0 = __ldg(gn + i * 4 + 0), i1 = __ldg(gn + i * 4 + 1);
    int i0c = max(i0, 0), i1c = max(i1, 0);
    float nf0u = g_node_f[i0c * 2 + 0];
    float nf1u = g_node_f[i0c * 2 + 1];
    float nA0 = (i0 >= 0) ? nf0u : 0.f;
    float nA1 = (i0 >= 0) ? nf1u : 0.f;
    float nB0 = (i1 >= 0) ? g_node_f[i1c * 2 + 0] : 0.f;
    float nB1 = (i1 >= 0) ? g_node_f[i1c * 2 + 1] : 0.f;
    float eA = g_eAB[i * 2 + 0], eB = g_eAB[i * 2 + 1];

    float cA, sA, cB, sB, c3a, s3a, c3b, s3b, c4a, s4a, c4b, s4b;
    __sincosf(0.5f * eA,  &sA,  &cA);
    __sincosf(0.5f * eB,  &sB,  &cB);
    __sincosf(0.5f * nA0, &s3a, &c3a);
    __sincosf(0.5f * nA1, &s3b, &c3b);
    __sincosf(0.5f * nB0, &s4a, &c4a);
    __sincosf(0.5f * nB1, &s4b, &c4b);

    // product init on q0,q4 (amps 0..3); q7=q8=|0>
    float f0r[2], f0i[2], f4r[2], f4i[2];
    f0r[0] = cA*cB;   f0i[0] = -cA*sB;   f0r[1] = sA*cB;   f0i[1] = sA*sB;
    f4r[0] = c4a*c4b; f4i[0] = -c4a*s4b; f4r[1] = s4a*c4b; f4i[1] = s4a*s4b;

    float cr[16], ci[16];
#pragma unroll
    for (int m = 0; m < 16; m++) { cr[m] = 0.f; ci[m] = 0.f; }
#pragma unroll
    for (int m = 0; m < 4; m++) {
        int b0 = m & 1, b4 = (m >> 1) & 1;
        cr[m] = f0r[b0]*f4r[b4] - f0i[b0]*f4i[b4];
        ci[m] = f0r[b0]*f4i[b4] + f0i[b0]*f4r[b4];
    }

    // CRX(nB0): c=q4(2), t=q7(4)
#pragma unroll
    for (int m = 0; m < 16; m++) if ((m & 2) && !(m & 4)) {
        int h = m | 4;
        float lr = cr[m], li = ci[m], hr = cr[h], hi = ci[h];
        cr[m] = c4a*lr + s4a*hi;  ci[m] = c4a*li - s4a*hr;
        cr[h] = c4a*hr + s4a*li;  ci[h] = c4a*hi - s4a*lr;
    }
    // CRY(eA): c=q0(1), t=q7(4)
#pragma unroll
    for (int m = 0; m < 16; m++) if ((m & 1) && !(m & 4)) {
        int h = m | 4;
        float lr = cr[m], li = ci[m], hr = cr[h], hi = ci[h];
        cr[m] = cA*lr - sA*hr;  ci[m] = cA*li - sA*hi;
        cr[h] = sA*lr + cA*hr;  ci[h] = sA*li + cA*hi;
    }
    // CRZ(nB1): c=q4(2), t=q8(8) — diagonal
#pragma unroll
    for (int m = 0; m < 16; m++) if (m & 2) {
        float r = cr[m], ii = ci[m];
        if (m & 8) { cr[m] = c4b*r - s4b*ii; ci[m] = c4b*ii + s4b*r; }
        else       { cr[m] = c4b*r + s4b*ii; ci[m] = c4b*ii - s4b*r; }
    }
    // CRY(eB): c=q0(1), t=q8(8)
#pragma unroll
    for (int m = 0; m < 16; m++) if ((m & 1) && !(m & 8)) {
        int h = m | 8;
        float lr = cr[m], li = ci[m], hr = cr[h], hi = ci[h];
        cr[m] = cB*lr - sB*hr;  ci[m] = cB*li - sB*hi;
        cr[h] = sB*lr + cB*hr;  ci[h] = sB*li + cB*hi;
    }

    float U[8];
#define LOADU(g) { _Pragma("unroll") for (int k = 0; k < 8; k++) U[k] = sU[g][k]; }
#define UGATE(B) { _Pragma("unroll") for (int m = 0; m < 16; m++) if (!(m & (B))) { \
    int h = m | (B); \
    float lr = cr[m], li = ci[m], hr = cr[h], hi = ci[h]; \
    cr[m] = U[0]*lr - U[1]*li + U[2]*hr - U[3]*hi; \
    ci[m] = U[0]*li + U[1]*lr + U[2]*hi + U[3]*hr; \
    cr[h] = U[4]*lr - U[5]*li + U[6]*hr - U[7]*hi; \
    ci[h] = U[4]*li + U[5]*lr + U[6]*hi + U[7]*hr; } }

    // Block 0: U0 q0, U1 q4, U2 q7; CZ(0,4) CZ(4,7) CZ(7,0)
    LOADU(0); UGATE(1)
    LOADU(1); UGATE(2)
    LOADU(2); UGATE(4)
#pragma unroll
    for (int m = 0; m < 16; m++) if (__popc(m & 7) >= 2) { cr[m] = -cr[m]; ci[m] = -ci[m]; }

    // Block 1: U3 q7, U4 q4, U5 q8; CZ(7,4) CZ(4,8) CZ(8,7)
    LOADU(3); UGATE(4)
    LOADU(4); UGATE(2)
    LOADU(5); UGATE(8)
#pragma unroll
    for (int m = 0; m < 16; m++) if (__popc(m & 14) >= 2) { cr[m] = -cr[m]; ci[m] = -ci[m]; }

    // S = <chi| M7(q7) (x) M8(q8) |chi>
    float d7 = sM[0], k7r = sM[1], k7i = sM[2];
    float d8 = sM[3], k8r = sM[4], k8i = sM[5];
    float S = 0.f;
#pragma unroll
    for (int p = 0; p < 4; p++) {
        int a = p, b = p + 4, A = p + 8, Bx = p + 12;
        // q8 action: u = (I x M8) chi on pairs (a,A) and (b,Bx)
        float uar = d8*cr[a] + k8r*cr[A] - k8i*ci[A];
        float uai = d8*ci[a] + k8r*ci[A] + k8i*cr[A];
        float uAr = k8r*cr[a] + k8i*ci[a] - d8*cr[A];
        float uAi = k8r*ci[a] - k8i*cr[a] - d8*ci[A];
        float ubr = d8*cr[b] + k8r*cr[Bx] - k8i*ci[Bx];
        float ubi = d8*ci[b] + k8r*ci[Bx] + k8i*cr[Bx];
        float uBr = k8r*cr[b] + k8i*ci[b] - d8*cr[Bx];
        float uBi = k8r*ci[b] - k8i*cr[b] - d8*ci[Bx];
        // q7 pair (a,b)
        S += d7*(cr[a]*uar + ci[a]*uai - (cr[b]*ubr + ci[b]*ubi));
        S += cr[a]*(k7r*ubr - k7i*ubi) + ci[a]*(k7r*ubi + k7i*ubr);
        S += cr[b]*(k7r*uar + k7i*uai) + ci[b]*(k7r*uai - k7i*uar);
        // q7 pair (A,Bx)
        S += d7*(cr[A]*uAr + ci[A]*uAi - (cr[Bx]*uBr + ci[Bx]*uBi));
        S += cr[A]*(k7r*uBr - k7i*uBi) + ci[A]*(k7r*uBi + k7i*uBr);
        S += cr[Bx]*(k7r*uAr + k7i*uAi) + ci[Bx]*(k7r*uAi - k7i*uAr);
    }

    // q3 scalar: a = U6 * (RZ(nA1) RY(nA0)|0>), w = 2 Re(conj(a0) a1)
    LOADU(6);
    {
        float p0r = c3a*c3b, p0i = -c3a*s3b, p1r = s3a*c3b, p1i = s3a*s3b;
        float a0r = U[0]*p0r - U[1]*p0i + U[2]*p1r - U[3]*p1i;
        float a0i = U[0]*p0i + U[1]*p0r + U[2]*p1i + U[3]*p1r;
        float a1r = U[4]*p0r - U[5]*p0i + U[6]*p1r - U[7]*p1i;
        float a1i = U[4]*p0i + U[5]*p0r + U[6]*p1i + U[7]*p1r;
        S *= 2.f * (a0r*a1r + a0i*a1i);
    }
    float ex = S;

    // upd MLP: 3 -> 128 (leaky) -> 2 (full per thread, broadcast LDS)
    float acc0 = sb2v[0], acc1 = sb2v[1];
#pragma unroll 8
    for (int j = 0; j < 128; j++) {
        float4 wv = sP1[j];
        float h = fmaf(nf0u, wv.x, fmaf(nf1u, wv.y, fmaf(ex, wv.z, wv.w)));
        h = leaky(h);
        float2 v = sP2[j];
        acc0 = fmaf(h, v.x, acc0);
        acc1 = fmaf(h, v.y, acc1);
    }

    if (valid) {
        if (mode == 1) {
            int gi = batch[i];
            atomicAdd(&g_seg[gi * 2 + 0], g_node_f[i * 2 + 0]);
            atomicAdd(&g_seg[gi * 2 + 1], g_node_f[i * 2 + 1]);
            atomicAdd(&g_cnt[gi], 1.f);
            int gt = batch[i0c];
            atomicAdd(&g_seg[gt * 2 + 0], acc0);
            atomicAdd(&g_seg[gt * 2 + 1], acc1);
        } else {
            g_upd[i * 2 + 0] = acc0;
            g_upd[i * 2 + 1] = acc1;
        }
    }

    // fused head: last block computes output
    if (mode == 1) {
        __threadfence();
        __syncthreads();
        if (tid == 0) s_last = (atomicAdd(&g_ctr, 1) == (int)gridDim.x - 1) ? 1 : 0;
        __syncthreads();
        if (s_last) {
            for (int g = tid; g < G; g += blockDim.x) {
                float c = ldcg(&g_cnt[g]);
                float inv = (c > 0.f) ? (1.f / c) : 0.f;
                float e0 = ldcg(&g_seg[g * 2 + 0]) * inv;
                float e1 = ldcg(&g_seg[g * 2 + 1]) * inv;
                float h0 = leaky(e0 * hW1[0] + e1 * hW1[2] + hb1[0]);
                float h1 = leaky(e0 * hW1[1] + e1 * hW1[3] + hb1[1]);
                out[g * 2 + 0] = h0 * hW2[0] + h1 * hW2[2] + hb2[0];
                out[g * 2 + 1] = h0 * hW2[1] + h1 * hW2[3] + hb2[1];
            }
        }
    }
}

// ---------------- multi-hop helpers (H > 1 only) ----------------------------
__global__ void k2_scatter(int N, const int* __restrict__ gn)
{
    int i = blockIdx.x * blockDim.x + threadIdx.x;
    if (i >= N) return;
    int t = max(gn[i * 4], 0);
    atomicAdd(&g_node_f[t * 2 + 0], g_upd[i * 2 + 0]);
    atomicAdd(&g_node_f[t * 2 + 1], g_upd[i * 2 + 1]);
}

__global__ void k_seg(int N, const int* __restrict__ batch)
{
    int i = blockIdx.x * blockDim.x + threadIdx.x;
    if (i >= N) return;
    int g = batch[i];
    atomicAdd(&g_seg[g * 2 + 0], g_node_f[i * 2 + 0]);
    atomicAdd(&g_seg[g * 2 + 1], g_node_f[i * 2 + 1]);
    atomicAdd(&g_cnt[g], 1.f);
}

__global__ void k3_head(int G,
                        const float* __restrict__ hW1, const float* __restrict__ hb1,
                        const float* __restrict__ hW2, const float* __restrict__ hb2,
                        float* __restrict__ out)
{
    int g = blockIdx.x * blockDim.x + threadIdx.x;
    if (g >= G) return;
    float c = g_cnt[g];
    float inv = (c > 0.f) ? (1.f / c) : 0.f;
    float e0 = g_seg[g * 2 + 0] * inv;
    float e1 = g_seg[g * 2 + 1] * inv;
    float h0 = leaky(e0 * hW1[0] + e1 * hW1[2] + hb1[0]);
    float h1 = leaky(e0 * hW1[1] + e1 * hW1[3] + hb1[1]);
    out[g * 2 + 0] = h0 * hW2[0] + h1 * hW2[2] + hb2[0];
    out[g * 2 + 1] = h0 * hW2[1] + h1 * hW2[3] + hb2[1];
}

extern "C" void kernel_launch(void* const* d_in, const int* in_sizes, int n_in,
                              void* d_out, int out_size)
{
    const float* node_feat = (const float*)d_in[0];
    const float* edge_attr = (const float*)d_in[1];
    const float* nW1 = (const float*)d_in[2];
    const float* nb1 = (const float*)d_in[3];
    const float* nW2 = (const float*)d_in[4];
    const float* nb2 = (const float*)d_in[5];
    const float* eW1 = (const float*)d_in[6];
    const float* eb1 = (const float*)d_in[7];
    const float* eW2 = (const float*)d_in[8];
    const float* eb2 = (const float*)d_in[9];
    const float* theta = (const float*)d_in[10];
    const float* uW1 = (const float*)d_in[11];
    const float* ub1 = (const float*)d_in[12];
    const float* uW2 = (const float*)d_in[13];
    const float* ub2 = (const float*)d_in[14];
    const float* hW1 = (const float*)d_in[15];
    const float* hb1 = (const float*)d_in[16];
    const float* hW2 = (const float*)d_in[17];
    const float* hb2 = (const float*)d_in[18];
    const int* gn = (const int*)d_in[19];
    const int* ge = (const int*)d_in[20];
    const int* batch = (const int*)d_in[21];

    int N = in_sizes[0] / 16;
    int H = in_sizes[10] / 27;
    int G = out_size / 2;

    int k1blocks = (N + 15) / 16;
    k1_feat<<<k1blocks, 128>>>(node_feat, N, edge_attr, nW1, nb1, nW2, nb2,
                               eW1, eb1, eW2, eb2, ge);

    // k2: one thread per row, 64-thread blocks
    int k2blocks = (N + 63) / 64;
    if (H == 1) {
        k2_pqc<<<k2blocks, 64>>>(N, 1, G, theta, uW1, ub1, uW2, ub2, gn, batch,
                                 hW1, hb1, hW2, hb2, (float*)d_out);
    } else {
        const int T = 128;
        int nbs = (N + T - 1) / T;
        for (int h = 0; h < H; h++) {
            k2_pqc<<<k2blocks, 64>>>(N, 0, G, theta + 27 * h,
                                     uW1 + 384 * h, ub1 + 128 * h,
                                     uW2 + 256 * h, ub2 + 2 * h, gn, batch,
                                     hW1, hb1, hW2, hb2, (float*)d_out);
            k2_scatter<<<nbs, T>>>(N, gn);
        }
        k_seg<<<nbs, T>>>(N, batch);
        k3_head<<<(G + 127) / 128, 128>>>(G, hW1, hb1, hW2, hb2, (float*)d_out);
    }
}